// round 2
// baseline (speedup 1.0000x reference)
#include <cuda_runtime.h>
#include <cstddef>

// ---------------------------------------------------------------------------
// Problem constants (from reference): B=8, S=1024, D=512, H=8, DK=D=512.
// ---------------------------------------------------------------------------
#define B_    8
#define S_    1024
#define D_    512
#define H_    8
#define DK_   512
#define HD_   4096          // H_*DK_

// ---------------------------------------------------------------------------
// Scratch (device globals; no runtime allocation allowed).
//   g_qh/g_kh/g_vh : (B,H,S,DK)  = 33,554,432 floats each (134 MB)
//   g_sc           : (B*H,S,S)   = 67,108,864 floats      (268 MB)
//   g_att          : (B,S,H*DK)  = 33,554,432 floats      (134 MB)
// ---------------------------------------------------------------------------
__device__ float g_qh[(size_t)B_ * H_ * S_ * DK_];
__device__ float g_kh[(size_t)B_ * H_ * S_ * DK_];
__device__ float g_vh[(size_t)B_ * H_ * S_ * DK_];
__device__ float g_sc[(size_t)B_ * H_ * S_ * S_];
__device__ float g_att[(size_t)B_ * S_ * HD_];

// ---------------------------------------------------------------------------
// Tiled SGEMM: C = A @ B (or A @ B^T), 128x128 tile, BK=8, 256 threads,
// 8x8 per-thread register block. All problem dims here are multiples of the
// tile sizes, so no bounds checks are needed.
//
// TRANSB = true : Bmat is [N,K] row-major (weight layout), C[m,n] = sum_k A[m,k]*Bmat[n,k]
// TRANSB = false: Bmat is [K,N] row-major,                 C[m,n] = sum_k A[m,k]*Bmat[k,n]
//
// EPI:
//   0 = plain batched store with scale          (scores)
//   1 = permute (B,S,H*DK) -> (B,H,S,DK)        (projections)
//   2 = permute (bh batch, S, DK) -> (B,S,H*DK) (P@V output)
//   3 = add residual, plain store               (fc)
// ---------------------------------------------------------------------------
#define BM 128
#define BN 128
#define BKK 8
#define TM 8
#define TN 8

template <bool TRANSB, int EPI>
__global__ void __launch_bounds__(256)
gemm_k(const float* __restrict__ A0, const float* __restrict__ B0,
       float* __restrict__ C0, const float* __restrict__ resid,
       int M, int N, int K,
       size_t strideA, size_t strideB, size_t strideC, float scale)
{
    __shared__ float As[BKK][BM];
    __shared__ float Bs[BKK][BN];

    const int tid = threadIdx.x;
    const int z   = blockIdx.z;

    const float* A  = A0 + (size_t)z * strideA;
    const float* Bm = B0 + (size_t)z * strideB;

    const int m0 = blockIdx.y * BM;
    const int n0 = blockIdx.x * BN;

    const int tx = tid & 15;        // 0..15 -> column group
    const int ty = tid >> 4;        // 0..15 -> row group

    // loader indices
    const int lr  = tid >> 1;       // 0..127 (row of A tile / row of W tile)
    const int lc  = (tid & 1) * 4;  // 0 or 4 (k offset)
    const int bkr = tid >> 5;       // 0..7   (k row, no-trans B)
    const int bnc = (tid & 31) * 4; // 0..124 (n col, no-trans B)

    float acc[TM][TN];
#pragma unroll
    for (int i = 0; i < TM; i++)
#pragma unroll
        for (int j = 0; j < TN; j++) acc[i][j] = 0.0f;

    for (int k0 = 0; k0 < K; k0 += BKK) {
        // load A tile (transposed into As[k][m])
        float4 av = *reinterpret_cast<const float4*>(&A[(size_t)(m0 + lr) * K + k0 + lc]);
        As[lc + 0][lr] = av.x;
        As[lc + 1][lr] = av.y;
        As[lc + 2][lr] = av.z;
        As[lc + 3][lr] = av.w;

        if (TRANSB) {
            float4 bv = *reinterpret_cast<const float4*>(&Bm[(size_t)(n0 + lr) * K + k0 + lc]);
            Bs[lc + 0][lr] = bv.x;
            Bs[lc + 1][lr] = bv.y;
            Bs[lc + 2][lr] = bv.z;
            Bs[lc + 3][lr] = bv.w;
        } else {
            float4 bv = *reinterpret_cast<const float4*>(&Bm[(size_t)(k0 + bkr) * N + n0 + bnc]);
            *reinterpret_cast<float4*>(&Bs[bkr][bnc]) = bv;
        }
        __syncthreads();

#pragma unroll
        for (int kk = 0; kk < BKK; kk++) {
            float ar[TM], br[TN];
#pragma unroll
            for (int i = 0; i < TM; i++) ar[i] = As[kk][ty * TM + i];
#pragma unroll
            for (int j = 0; j < TN; j++) br[j] = Bs[kk][tx * TN + j];
#pragma unroll
            for (int i = 0; i < TM; i++)
#pragma unroll
                for (int j = 0; j < TN; j++)
                    acc[i][j] = fmaf(ar[i], br[j], acc[i][j]);
        }
        __syncthreads();
    }

    // -------- epilogue --------
    float* C = C0 + (size_t)z * strideC;

#pragma unroll
    for (int i = 0; i < TM; i++) {
        const int m = m0 + ty * TM + i;
#pragma unroll
        for (int j = 0; j < TN; j += 4) {
            const int n = n0 + tx * TN + j;
            float4 v = make_float4(acc[i][j + 0] * scale,
                                   acc[i][j + 1] * scale,
                                   acc[i][j + 2] * scale,
                                   acc[i][j + 3] * scale);
            if constexpr (EPI == 0) {
                *reinterpret_cast<float4*>(&C[(size_t)m * N + n]) = v;
            } else if constexpr (EPI == 1) {
                // m = b*S+s in [0,8192), n = h*DK+d in [0,4096)
                const int b = m >> 10, s = m & (S_ - 1);
                const int h = n >> 9,  d = n & (DK_ - 1);
                *reinterpret_cast<float4*>(
                    &C[(((size_t)(b * H_ + h)) * S_ + s) * DK_ + d]) = v;
            } else if constexpr (EPI == 2) {
                // z = b*H+h, m = s, n = d
                const int b = z >> 3, h = z & (H_ - 1);
                *reinterpret_cast<float4*>(
                    &C[((size_t)(b * S_ + m)) * HD_ + h * DK_ + n]) = v;
            } else { // EPI == 3 : residual add
                const float* r = &resid[(size_t)m * N + n];
                v.x += r[0]; v.y += r[1]; v.z += r[2]; v.w += r[3];
                *reinterpret_cast<float4*>(&C[(size_t)m * N + n]) = v;
            }
        }
    }
}

// ---------------------------------------------------------------------------
// Row softmax over length-1024 rows. One block (256 threads) per row.
// ---------------------------------------------------------------------------
__global__ void __launch_bounds__(256) softmax_k(float* __restrict__ sc)
{
    const size_t row = blockIdx.x;
    float4* p = reinterpret_cast<float4*>(sc) + row * 256 + threadIdx.x;
    float4 v = *p;

    __shared__ float red[8];

    float m = fmaxf(fmaxf(v.x, v.y), fmaxf(v.z, v.w));
#pragma unroll
    for (int o = 16; o; o >>= 1) m = fmaxf(m, __shfl_xor_sync(0xffffffffu, m, o));
    if ((threadIdx.x & 31) == 0) red[threadIdx.x >> 5] = m;
    __syncthreads();
    m = red[0];
#pragma unroll
    for (int i = 1; i < 8; i++) m = fmaxf(m, red[i]);

    v.x = expf(v.x - m); v.y = expf(v.y - m);
    v.z = expf(v.z - m); v.w = expf(v.w - m);

    float s = v.x + v.y + v.z + v.w;
#pragma unroll
    for (int o = 16; o; o >>= 1) s += __shfl_xor_sync(0xffffffffu, s, o);
    __syncthreads();                 // protect red[] reuse
    if ((threadIdx.x & 31) == 0) red[threadIdx.x >> 5] = s;
    __syncthreads();
    s = 0.0f;
#pragma unroll
    for (int i = 0; i < 8; i++) s += red[i];

    const float inv = 1.0f / s;
    v.x *= inv; v.y *= inv; v.z *= inv; v.w *= inv;
    *p = v;
}

// ---------------------------------------------------------------------------
// LayerNorm over length-512 rows, in-place on d_out. One block per row.
// ---------------------------------------------------------------------------
__global__ void __launch_bounds__(256) ln_k(float* __restrict__ out,
                                            const float* __restrict__ gamma,
                                            const float* __restrict__ beta)
{
    const size_t row = blockIdx.x;
    float2* p = reinterpret_cast<float2*>(out) + row * 256 + threadIdx.x;
    float2 v = *p;

    float s  = v.x + v.y;
    float ss = v.x * v.x + v.y * v.y;

    __shared__ float r1[8], r2[8];
#pragma unroll
    for (int o = 16; o; o >>= 1) {
        s  += __shfl_xor_sync(0xffffffffu, s, o);
        ss += __shfl_xor_sync(0xffffffffu, ss, o);
    }
    if ((threadIdx.x & 31) == 0) { r1[threadIdx.x >> 5] = s; r2[threadIdx.x >> 5] = ss; }
    __syncthreads();
    s = 0.0f; ss = 0.0f;
#pragma unroll
    for (int i = 0; i < 8; i++) { s += r1[i]; ss += r2[i]; }

    const float mu  = s * (1.0f / 512.0f);
    const float var = ss * (1.0f / 512.0f) - mu * mu;
    const float inv = rsqrtf(var + 1e-6f);

    const int c = threadIdx.x * 2;
    v.x = (v.x - mu) * inv * gamma[c + 0] + beta[c + 0];
    v.y = (v.y - mu) * inv * gamma[c + 1] + beta[c + 1];
    *p = v;
}

// ---------------------------------------------------------------------------
// Launch. Inputs (metadata order): q,k,v,w_q,w_k,w_v,w_fc,gamma,beta.
// Output: fp32 (B,S,D) = 8192x512.
// ---------------------------------------------------------------------------
extern "C" void kernel_launch(void* const* d_in, const int* in_sizes, int n_in,
                              void* d_out, int out_size)
{
    const float* in_q  = (const float*)d_in[0];
    const float* in_k  = (const float*)d_in[1];
    const float* in_v  = (const float*)d_in[2];
    const float* w_q   = (const float*)d_in[3];
    const float* w_k   = (const float*)d_in[4];
    const float* w_v   = (const float*)d_in[5];
    const float* w_fc  = (const float*)d_in[6];
    const float* gamma = (const float*)d_in[7];
    const float* beta  = (const float*)d_in[8];
    float* out = (float*)d_out;

    float *qh, *kh, *vh, *sc, *att;
    cudaGetSymbolAddress((void**)&qh,  g_qh);
    cudaGetSymbolAddress((void**)&kh,  g_kh);
    cudaGetSymbolAddress((void**)&vh,  g_vh);
    cudaGetSymbolAddress((void**)&sc,  g_sc);
    cudaGetSymbolAddress((void**)&att, g_att);

    const dim3 blk(256);
    const float SCALE = 0.044194173824159216f;   // 1/sqrt(512)

    // 1) Projections: (8192x512)@(512x4096)^T -> permuted to (B,H,S,DK)
    const dim3 gp(HD_ / BN, (B_ * S_) / BM, 1);
    gemm_k<true, 1><<<gp, blk>>>(in_q, w_q, qh, nullptr, B_ * S_, HD_, D_, 0, 0, 0, 1.0f);
    gemm_k<true, 1><<<gp, blk>>>(in_k, w_k, kh, nullptr, B_ * S_, HD_, D_, 0, 0, 0, 1.0f);
    gemm_k<true, 1><<<gp, blk>>>(in_v, w_v, vh, nullptr, B_ * S_, HD_, D_, 0, 0, 0, 1.0f);

    // 2) Scores: per (b,h), (1024x512)@(1024x512)^T * scale
    const dim3 gs(S_ / BN, S_ / BM, B_ * H_);
    gemm_k<true, 0><<<gs, blk>>>(qh, kh, sc, nullptr, S_, S_, DK_,
                                 (size_t)S_ * DK_, (size_t)S_ * DK_,
                                 (size_t)S_ * S_, SCALE);

    // 3) Row softmax over 64*1024 rows of 1024
    softmax_k<<<B_ * H_ * S_, 256>>>(sc);

    // 4) P@V: per (b,h), (1024x1024)@(1024x512) -> permuted to (B,S,H*DK)
    const dim3 gv(DK_ / BN, S_ / BM, B_ * H_);
    gemm_k<false, 2><<<gv, blk>>>(sc, vh, att, nullptr, S_, DK_, S_,
                                  (size_t)S_ * S_, (size_t)S_ * DK_, 0, 1.0f);

    // 5) fc: (8192x4096)@(512x4096)^T + residual -> d_out
    const dim3 gf(D_ / BN, (B_ * S_) / BM, 1);
    gemm_k<true, 3><<<gf, blk>>>(att, w_fc, out, in_q, B_ * S_, D_, HD_, 0, 0, 0, 1.0f);

    // 6) LayerNorm in-place on d_out
    ln_k<<<B_ * S_, 256>>>(out, gamma, beta);
}

// round 5
// speedup vs baseline: 2.7363x; 2.7363x over previous
#include <cuda_runtime.h>
#include <cuda_bf16.h>
#include <cstdint>
#include <cstddef>

#define B_    8
#define S_    1024
#define D_    512
#define H_    8
#define DK_   512
#define HD_   4096

typedef __nv_bfloat16 bf16;

// ---------------- scratch (device globals; no runtime alloc) ----------------
__device__ float g_sc   [(size_t)B_*H_*S_*S_];

__device__ bf16 g_q_hi [(size_t)B_*S_*D_];
__device__ bf16 g_q_lo [(size_t)B_*S_*D_];
__device__ bf16 g_k_hi [(size_t)B_*S_*D_];
__device__ bf16 g_k_lo [(size_t)B_*S_*D_];
__device__ bf16 g_v_hi [(size_t)B_*S_*D_];
__device__ bf16 g_v_lo [(size_t)B_*S_*D_];

__device__ bf16 g_wq_hi[(size_t)HD_*D_];
__device__ bf16 g_wq_lo[(size_t)HD_*D_];
__device__ bf16 g_wk_hi[(size_t)HD_*D_];
__device__ bf16 g_wk_lo[(size_t)HD_*D_];
__device__ bf16 g_wv_hi[(size_t)HD_*D_];
__device__ bf16 g_wv_lo[(size_t)HD_*D_];
__device__ bf16 g_wf_hi[(size_t)D_*HD_];
__device__ bf16 g_wf_lo[(size_t)D_*HD_];

__device__ bf16 g_qh_hi[(size_t)B_*H_*S_*DK_];
__device__ bf16 g_qh_lo[(size_t)B_*H_*S_*DK_];
__device__ bf16 g_kh_hi[(size_t)B_*H_*S_*DK_];
__device__ bf16 g_kh_lo[(size_t)B_*H_*S_*DK_];
__device__ bf16 g_vh_hi[(size_t)B_*H_*S_*DK_];   // V heads (z, s, d)
__device__ bf16 g_vh_lo[(size_t)B_*H_*S_*DK_];
__device__ bf16 g_vt_hi[(size_t)B_*H_*DK_*S_];   // V transposed (z, d, s)
__device__ bf16 g_vt_lo[(size_t)B_*H_*DK_*S_];

__device__ bf16 g_p_hi [(size_t)B_*H_*S_*S_];
__device__ bf16 g_p_lo [(size_t)B_*H_*S_*S_];

__device__ bf16 g_at_hi[(size_t)B_*S_*HD_];
__device__ bf16 g_at_lo[(size_t)B_*S_*HD_];

// ---------------- helpers ----------------
__device__ __forceinline__ uint32_t smem_u32(const void* p) {
    uint32_t a;
    asm("{ .reg .u64 t; cvta.to.shared.u64 t, %1; cvt.u32.u64 %0, t; }"
        : "=r"(a) : "l"(p));
    return a;
}
__device__ __forceinline__ void cp16(uint32_t s, const void* g) {
    asm volatile("cp.async.cg.shared.global [%0], [%1], 16;" :: "r"(s), "l"(g));
}
__device__ __forceinline__ void cp_commit() { asm volatile("cp.async.commit_group;"); }
template <int N> __device__ __forceinline__ void cp_wait() {
    asm volatile("cp.async.wait_group %0;" :: "n"(N));
}
__device__ __forceinline__ void ldsm4(uint32_t* r, uint32_t a) {
    asm volatile("ldmatrix.sync.aligned.m8n8.x4.shared.b16 {%0,%1,%2,%3}, [%4];"
                 : "=r"(r[0]), "=r"(r[1]), "=r"(r[2]), "=r"(r[3]) : "r"(a));
}
__device__ __forceinline__ void ldsm2(uint32_t* r, uint32_t a) {
    asm volatile("ldmatrix.sync.aligned.m8n8.x2.shared.b16 {%0,%1}, [%2];"
                 : "=r"(r[0]), "=r"(r[1]) : "r"(a));
}
__device__ __forceinline__ void mma16816(float* d, const uint32_t* a, const uint32_t* b) {
    asm volatile("mma.sync.aligned.m16n8k16.row.col.f32.bf16.bf16.f32 "
                 "{%0,%1,%2,%3}, {%4,%5,%6,%7}, {%8,%9}, {%0,%1,%2,%3};"
                 : "+f"(d[0]), "+f"(d[1]), "+f"(d[2]), "+f"(d[3])
                 : "r"(a[0]), "r"(a[1]), "r"(a[2]), "r"(a[3]),
                   "r"(b[0]), "r"(b[1]));
}
__device__ __forceinline__ uint32_t pack2(bf16 a, bf16 b) {
    return (uint32_t)__bfloat16_as_ushort(a) | ((uint32_t)__bfloat16_as_ushort(b) << 16);
}
__device__ __forceinline__ void split2(float v0, float v1, uint32_t& hi, uint32_t& lo) {
    const bf16 h0 = __float2bfloat16_rn(v0), h1 = __float2bfloat16_rn(v1);
    hi = pack2(h0, h1);
    lo = pack2(__float2bfloat16_rn(v0 - __bfloat162float(h0)),
               __float2bfloat16_rn(v1 - __bfloat162float(h1)));
}

// tile-row swizzle: 16B chunk c of row r goes to chunk c ^ ((r ^ (r>>2)) & 3)
__device__ __forceinline__ uint32_t swz(int r, int c) {
    return (uint32_t)(r * 64 + ((c ^ ((r ^ (r >> 2)) & 3)) << 4));
}

// ---------------------------------------------------------------------------
// bf16x3 HMMA GEMM: C[m,n] = sum_k A[m,k]*B[n,k]  (both K-major),
// computed as Ahi*Bhi + Ahi*Blo + Alo*Bhi, fp32 accumulators.
// CTA 128x128, 8 warps (2m x 4n) of 64x32 warp tiles, BK=32, 4-stage cp.async.
// ---------------------------------------------------------------------------
#define NSTAGES 4
#define STAGE_BYTES 16384     // A 8KB + B 8KB
#define SMEMSZ (NSTAGES * STAGE_BYTES)

enum { EPI_SCORES = 0, EPI_PROJ = 1, EPI_ATT = 2, EPI_FC = 3 };

template <int EPI>
__global__ void __launch_bounds__(256, 2)
gemm3(const bf16* __restrict__ Ahi, const bf16* __restrict__ Alo,
      const bf16* __restrict__ Bhi, const bf16* __restrict__ Blo,
      float* __restrict__ Cf, bf16* __restrict__ Chi, bf16* __restrict__ Clo,
      const float* __restrict__ resid,
      int K, long long strideA, long long strideB, float scale)
{
    extern __shared__ __align__(128) char smem[];
    const uint32_t sb = smem_u32(smem);
    const int tid  = threadIdx.x;
    const int wid  = tid >> 5;
    const int lane = tid & 31;
    const int wm = wid & 1;          // 2 m-groups of 64
    const int wn = wid >> 1;         // 4 n-groups of 32
    const int m0 = blockIdx.y * 128;
    const int n0 = blockIdx.x * 128;
    const int z  = blockIdx.z;

    const bf16* Aps[3] = { Ahi + (size_t)z * strideA, Ahi + (size_t)z * strideA,
                           Alo + (size_t)z * strideA };
    const bf16* Bps[3] = { Bhi + (size_t)z * strideB, Blo + (size_t)z * strideB,
                           Bhi + (size_t)z * strideB };

    const int NK = 3 * (K >> 5);

    auto load_iter = [&](int j, int stage) {
        const int t = j / 3, c3 = j - 3 * t;   // combo innermost -> L2 reuse
        const bf16* Ap = Aps[c3];
        const bf16* Bp = Bps[c3];
        const uint32_t sA = sb + (uint32_t)stage * STAGE_BYTES;
        const uint32_t sB = sA + 8192;
        const int kb = t * 32;
#pragma unroll
        for (int i = 0; i < 2; i++) {
            const int chunk = i * 256 + tid;   // 512 chunks: 128 rows x 4
            const int r = chunk >> 2, c = chunk & 3;
            cp16(sA + swz(r, c), Ap + (size_t)(m0 + r) * K + kb + c * 8);
        }
#pragma unroll
        for (int i = 0; i < 2; i++) {
            const int chunk = i * 256 + tid;
            const int r = chunk >> 2, c = chunk & 3;
            cp16(sB + swz(r, c), Bp + (size_t)(n0 + r) * K + kb + c * 8);
        }
    };

    float acc[4][4][4];
#pragma unroll
    for (int a = 0; a < 4; a++)
#pragma unroll
        for (int b = 0; b < 4; b++)
#pragma unroll
            for (int c = 0; c < 4; c++) acc[a][b][c] = 0.0f;

    load_iter(0, 0); cp_commit();
    load_iter(1, 1); cp_commit();
    load_iter(2, 2); cp_commit();

    for (int i = 0; i < NK; i++) {
        cp_wait<2>();
        __syncthreads();
        const uint32_t sA = sb + (uint32_t)(i & 3) * STAGE_BYTES;
        const uint32_t sB = sA + 8192;

#pragma unroll
        for (int q = 0; q < 2; q++) {
            uint32_t bfr[4][2];
#pragma unroll
            for (int ni = 0; ni < 4; ni++) {
                const int nr = wn * 32 + ni * 8 + (lane & 7);
                const int c  = q * 2 + ((lane >> 3) & 1);
                ldsm2(bfr[ni], sB + swz(nr, c));
            }
#pragma unroll
            for (int mi = 0; mi < 4; mi++) {
                uint32_t afr[4];
                const int mr = wm * 64 + mi * 16 + (lane & 15);
                const int c  = q * 2 + (lane >> 4);
                ldsm4(afr, sA + swz(mr, c));
#pragma unroll
                for (int ni = 0; ni < 4; ni++)
                    mma16816(acc[mi][ni], afr, bfr[ni]);
            }
        }

        const int j = i + 3;
        if (j < NK) load_iter(j, j & 3);
        cp_commit();
    }

    // ---------------- epilogue ----------------
    const int l4 = lane >> 2;            // row within 8
    const int l2 = (lane & 3) * 2;       // col pair
#pragma unroll
    for (int mi = 0; mi < 4; mi++) {
#pragma unroll
        for (int h2 = 0; h2 < 2; h2++) {
            const int row = m0 + wm * 64 + mi * 16 + l4 + h2 * 8;
#pragma unroll
            for (int ni = 0; ni < 4; ni++) {
                const int col = n0 + wn * 32 + ni * 8 + l2;
                const float v0 = acc[mi][ni][2 * h2 + 0];
                const float v1 = acc[mi][ni][2 * h2 + 1];

                if constexpr (EPI == EPI_SCORES) {
                    float* p = Cf + (size_t)z * S_ * S_ + (size_t)row * S_ + col;
                    *reinterpret_cast<float2*>(p) = make_float2(v0 * scale, v1 * scale);
                } else if constexpr (EPI == EPI_FC) {
                    const size_t base = (size_t)row * D_ + col;
                    const float2 rv = *reinterpret_cast<const float2*>(resid + base);
                    *reinterpret_cast<float2*>(Cf + base) =
                        make_float2(v0 + rv.x, v1 + rv.y);
                } else if constexpr (EPI == EPI_PROJ) {
                    const int b = row >> 10, s = row & (S_ - 1);
                    const int hh = col >> 9, d = col & (DK_ - 1);
                    const size_t base = (((size_t)(b * H_ + hh)) * S_ + s) * DK_ + d;
                    uint32_t hi, lo;
                    split2(v0, v1, hi, lo);
                    *reinterpret_cast<uint32_t*>(Chi + base) = hi;
                    *reinterpret_cast<uint32_t*>(Clo + base) = lo;
                } else { // EPI_ATT
                    const int b = z >> 3, hh = z & (H_ - 1);
                    const size_t base = ((size_t)(b * S_ + row)) * HD_ + hh * DK_ + col;
                    uint32_t hi, lo;
                    split2(v0, v1, hi, lo);
                    *reinterpret_cast<uint32_t*>(Chi + base) = hi;
                    *reinterpret_cast<uint32_t*>(Clo + base) = lo;
                }
            }
        }
    }
}

// ---------------- fp32 -> (hi, lo) bf16 split ----------------
__global__ void __launch_bounds__(256) conv_k(const float* __restrict__ s,
                                              bf16* __restrict__ hi,
                                              bf16* __restrict__ lo, int n)
{
    const int i = (blockIdx.x * 256 + threadIdx.x) * 4;
    if (i >= n) return;
    float4 v = *reinterpret_cast<const float4*>(s + i);
    uint32_t h0, l0, h1, l1;
    split2(v.x, v.y, h0, l0);
    split2(v.z, v.w, h1, l1);
    *reinterpret_cast<uint2*>(hi + i) = make_uint2(h0, h1);
    *reinterpret_cast<uint2*>(lo + i) = make_uint2(l0, l1);
}

// ---------------- V transpose: (z, s, d) -> (z, d, s), 64x64 tiles ----------
__global__ void __launch_bounds__(256) transp_k(const bf16* __restrict__ in_hi,
                                                const bf16* __restrict__ in_lo,
                                                bf16* __restrict__ out_hi,
                                                bf16* __restrict__ out_lo)
{
    __shared__ bf16 t[64][72];
    const int zz  = blockIdx.z >> 1;
    const bf16* in = (blockIdx.z & 1) ? in_lo : in_hi;
    bf16* out      = (blockIdx.z & 1) ? out_lo : out_hi;
    const int d0 = blockIdx.x * 64, s0 = blockIdx.y * 64;
    const int tid = threadIdx.x;
    const int rs = tid >> 2, cb = (tid & 3) * 16;

    const bf16* src = in + ((size_t)zz * S_ + s0 + rs) * DK_ + d0 + cb;
    *reinterpret_cast<uint4*>(&t[rs][cb])     = reinterpret_cast<const uint4*>(src)[0];
    *reinterpret_cast<uint4*>(&t[rs][cb + 8]) = reinterpret_cast<const uint4*>(src)[1];
    __syncthreads();

    bf16 buf[16];
#pragma unroll
    for (int j = 0; j < 16; j++) buf[j] = t[cb + j][rs];
    bf16* dst = out + ((size_t)zz * DK_ + d0 + rs) * S_ + s0 + cb;
    reinterpret_cast<uint4*>(dst)[0] = *reinterpret_cast<uint4*>(&buf[0]);
    reinterpret_cast<uint4*>(dst)[1] = *reinterpret_cast<uint4*>(&buf[8]);
}

// ---------------- row softmax (len 1024) -> bf16 hi/lo probs ----------------
__global__ void __launch_bounds__(256) softmax_k(const float* __restrict__ sc,
                                                 bf16* __restrict__ phi,
                                                 bf16* __restrict__ plo)
{
    const size_t row = blockIdx.x;
    const float4* p = reinterpret_cast<const float4*>(sc) + row * 256 + threadIdx.x;
    float4 v = *p;

    __shared__ float red[8];

    float m = fmaxf(fmaxf(v.x, v.y), fmaxf(v.z, v.w));
#pragma unroll
    for (int o = 16; o; o >>= 1) m = fmaxf(m, __shfl_xor_sync(0xffffffffu, m, o));
    if ((threadIdx.x & 31) == 0) red[threadIdx.x >> 5] = m;
    __syncthreads();
    m = red[0];
#pragma unroll
    for (int i = 1; i < 8; i++) m = fmaxf(m, red[i]);

    v.x = expf(v.x - m); v.y = expf(v.y - m);
    v.z = expf(v.z - m); v.w = expf(v.w - m);

    float s = v.x + v.y + v.z + v.w;
#pragma unroll
    for (int o = 16; o; o >>= 1) s += __shfl_xor_sync(0xffffffffu, s, o);
    __syncthreads();
    if ((threadIdx.x & 31) == 0) red[threadIdx.x >> 5] = s;
    __syncthreads();
    s = 0.0f;
#pragma unroll
    for (int i = 0; i < 8; i++) s += red[i];

    const float inv = 1.0f / s;
    v.x *= inv; v.y *= inv; v.z *= inv; v.w *= inv;

    const size_t base = row * 1024 + threadIdx.x * 4;
    uint32_t h0, l0, h1, l1;
    split2(v.x, v.y, h0, l0);
    split2(v.z, v.w, h1, l1);
    *reinterpret_cast<uint2*>(phi + base) = make_uint2(h0, h1);
    *reinterpret_cast<uint2*>(plo + base) = make_uint2(l0, l1);
}

// ---------------- LayerNorm (len 512), in-place ----------------
__global__ void __launch_bounds__(256) ln_k(float* __restrict__ out,
                                            const float* __restrict__ gamma,
                                            const float* __restrict__ beta)
{
    const size_t row = blockIdx.x;
    float2* p = reinterpret_cast<float2*>(out) + row * 256 + threadIdx.x;
    float2 v = *p;

    float s  = v.x + v.y;
    float ss = v.x * v.x + v.y * v.y;

    __shared__ float r1[8], r2[8];
#pragma unroll
    for (int o = 16; o; o >>= 1) {
        s  += __shfl_xor_sync(0xffffffffu, s, o);
        ss += __shfl_xor_sync(0xffffffffu, ss, o);
    }
    if ((threadIdx.x & 31) == 0) { r1[threadIdx.x >> 5] = s; r2[threadIdx.x >> 5] = ss; }
    __syncthreads();
    s = 0.0f; ss = 0.0f;
#pragma unroll
    for (int i = 0; i < 8; i++) { s += r1[i]; ss += r2[i]; }

    const float mu  = s * (1.0f / 512.0f);
    const float var = ss * (1.0f / 512.0f) - mu * mu;
    const float inv = rsqrtf(var + 1e-6f);

    const int c = threadIdx.x * 2;
    v.x = (v.x - mu) * inv * gamma[c + 0] + beta[c + 0];
    v.y = (v.y - mu) * inv * gamma[c + 1] + beta[c + 1];
    *p = v;
}

// ---------------------------------------------------------------------------
extern "C" void kernel_launch(void* const* d_in, const int* in_sizes, int n_in,
                              void* d_out, int out_size)
{
    const float* in_q  = (const float*)d_in[0];
    const float* in_k  = (const float*)d_in[1];
    const float* in_v  = (const float*)d_in[2];
    const float* w_q   = (const float*)d_in[3];
    const float* w_k   = (const float*)d_in[4];
    const float* w_v   = (const float*)d_in[5];
    const float* w_fc  = (const float*)d_in[6];
    const float* gamma = (const float*)d_in[7];
    const float* beta  = (const float*)d_in[8];
    float* out = (float*)d_out;

    cudaFuncSetAttribute(gemm3<EPI_SCORES>, cudaFuncAttributeMaxDynamicSharedMemorySize, SMEMSZ);
    cudaFuncSetAttribute(gemm3<EPI_PROJ>,   cudaFuncAttributeMaxDynamicSharedMemorySize, SMEMSZ);
    cudaFuncSetAttribute(gemm3<EPI_ATT>,    cudaFuncAttributeMaxDynamicSharedMemorySize, SMEMSZ);
    cudaFuncSetAttribute(gemm3<EPI_FC>,     cudaFuncAttributeMaxDynamicSharedMemorySize, SMEMSZ);

    bf16 *qhi, *qlo, *khi, *klo, *vhi, *vlo;
    bf16 *wqh, *wql, *wkh, *wkl, *wvh, *wvl, *wfh, *wfl;
    bf16 *qhh, *qhl, *khh, *khl, *vhh, *vhl, *vth, *vtl, *phh, *phl, *ath, *atl;
    float *sc;
    cudaGetSymbolAddress((void**)&sc,  g_sc);
    cudaGetSymbolAddress((void**)&qhi, g_q_hi);  cudaGetSymbolAddress((void**)&qlo, g_q_lo);
    cudaGetSymbolAddress((void**)&khi, g_k_hi);  cudaGetSymbolAddress((void**)&klo, g_k_lo);
    cudaGetSymbolAddress((void**)&vhi, g_v_hi);  cudaGetSymbolAddress((void**)&vlo, g_v_lo);
    cudaGetSymbolAddress((void**)&wqh, g_wq_hi); cudaGetSymbolAddress((void**)&wql, g_wq_lo);
    cudaGetSymbolAddress((void**)&wkh, g_wk_hi); cudaGetSymbolAddress((void**)&wkl, g_wk_lo);
    cudaGetSymbolAddress((void**)&wvh, g_wv_hi); cudaGetSymbolAddress((void**)&wvl, g_wv_lo);
    cudaGetSymbolAddress((void**)&wfh, g_wf_hi); cudaGetSymbolAddress((void**)&wfl, g_wf_lo);
    cudaGetSymbolAddress((void**)&qhh, g_qh_hi); cudaGetSymbolAddress((void**)&qhl, g_qh_lo);
    cudaGetSymbolAddress((void**)&khh, g_kh_hi); cudaGetSymbolAddress((void**)&khl, g_kh_lo);
    cudaGetSymbolAddress((void**)&vhh, g_vh_hi); cudaGetSymbolAddress((void**)&vhl, g_vh_lo);
    cudaGetSymbolAddress((void**)&vth, g_vt_hi); cudaGetSymbolAddress((void**)&vtl, g_vt_lo);
    cudaGetSymbolAddress((void**)&phh, g_p_hi);  cudaGetSymbolAddress((void**)&phl, g_p_lo);
    cudaGetSymbolAddress((void**)&ath, g_at_hi); cudaGetSymbolAddress((void**)&atl, g_at_lo);

    const int NX = B_ * S_ * D_;     // 4M
    const int NW = HD_ * D_;         // 2M
    conv_k<<<NX / 1024, 256>>>(in_q, qhi, qlo, NX);
    conv_k<<<NX / 1024, 256>>>(in_k, khi, klo, NX);
    conv_k<<<NX / 1024, 256>>>(in_v, vhi, vlo, NX);
    conv_k<<<NW / 1024, 256>>>(w_q, wqh, wql, NW);
    conv_k<<<NW / 1024, 256>>>(w_k, wkh, wkl, NW);
    conv_k<<<NW / 1024, 256>>>(w_v, wvh, wvl, NW);
    conv_k<<<NW / 1024, 256>>>(w_fc, wfh, wfl, NW);

    const float SCALE = 0.044194173824159216f;   // 1/sqrt(512)

    // 1) projections (M=8192, N=4096, K=512) -> (z, s, d) hi/lo
    const dim3 gp(HD_ / 128, (B_ * S_) / 128, 1);
    gemm3<EPI_PROJ><<<gp, 256, SMEMSZ>>>(qhi, qlo, wqh, wql, nullptr, qhh, qhl, nullptr, D_, 0, 0, 1.0f);
    gemm3<EPI_PROJ><<<gp, 256, SMEMSZ>>>(khi, klo, wkh, wkl, nullptr, khh, khl, nullptr, D_, 0, 0, 1.0f);
    gemm3<EPI_PROJ><<<gp, 256, SMEMSZ>>>(vhi, vlo, wvh, wvl, nullptr, vhh, vhl, nullptr, D_, 0, 0, 1.0f);

    // 1b) V transpose: (z,s,d) -> (z,d,s) so PV stays row.col (B = V^T K-major)
    transp_k<<<dim3(DK_ / 64, S_ / 64, B_ * H_ * 2), 256>>>(vhh, vhl, vth, vtl);

    // 2) scores (per z: M=N=1024, K=512), scaled
    const dim3 gs(S_ / 128, S_ / 128, B_ * H_);
    gemm3<EPI_SCORES><<<gs, 256, SMEMSZ>>>(qhh, qhl, khh, khl, sc, nullptr, nullptr, nullptr,
                                           DK_, (long long)S_ * DK_, (long long)S_ * DK_, SCALE);

    // 3) softmax -> P hi/lo
    softmax_k<<<B_ * H_ * S_, 256>>>(sc, phh, phl);

    // 4) P @ V (per z: M=1024, N=512, K=1024; B = V^T)
    const dim3 gv(DK_ / 128, S_ / 128, B_ * H_);
    gemm3<EPI_ATT><<<gv, 256, SMEMSZ>>>(phh, phl, vth, vtl, nullptr, ath, atl, nullptr,
                                        S_, (long long)S_ * S_, (long long)DK_ * S_, 1.0f);

    // 5) fc + residual (M=8192, N=512, K=4096)
    const dim3 gf(D_ / 128, (B_ * S_) / 128, 1);
    gemm3<EPI_FC><<<gf, 256, SMEMSZ>>>(ath, atl, wfh, wfl, out, nullptr, nullptr, in_q,
                                       HD_, 0, 0, 1.0f);

    // 6) LayerNorm
    ln_k<<<B_ * S_, 256>>>(out, gamma, beta);
}

// round 6
// speedup vs baseline: 7.2824x; 2.6614x over previous
#include <cuda_runtime.h>
#include <cuda_fp16.h>
#include <cstdint>
#include <cstddef>

#define B_    8
#define S_    1024
#define D_    512
#define H_    8
#define DK_   512
#define HD_   4096

typedef __half fp16;

// ---------------- scratch (device globals; no runtime alloc) ----------------
__device__ float g_sc [(size_t)B_*H_*S_*S_];          // fp32 scores

__device__ fp16 g_q  [(size_t)B_*S_*D_];
__device__ fp16 g_k  [(size_t)B_*S_*D_];
__device__ fp16 g_v  [(size_t)B_*S_*D_];
__device__ fp16 g_wq [(size_t)HD_*D_];
__device__ fp16 g_wk [(size_t)HD_*D_];
__device__ fp16 g_wv [(size_t)HD_*D_];
__device__ fp16 g_wf [(size_t)D_*HD_];

__device__ fp16 g_qh [(size_t)B_*H_*S_*DK_];
__device__ fp16 g_kh [(size_t)B_*H_*S_*DK_];
__device__ fp16 g_vh [(size_t)B_*H_*S_*DK_];          // V heads (z, s, d)
__device__ fp16 g_vt [(size_t)B_*H_*DK_*S_];          // V transposed (z, d, s)
__device__ fp16 g_p  [(size_t)B_*H_*S_*S_];           // softmax probs
__device__ fp16 g_at [(size_t)B_*S_*HD_];             // attention output

// ---------------- helpers ----------------
__device__ __forceinline__ uint32_t smem_u32(const void* p) {
    uint32_t a;
    asm("{ .reg .u64 t; cvta.to.shared.u64 t, %1; cvt.u32.u64 %0, t; }"
        : "=r"(a) : "l"(p));
    return a;
}
__device__ __forceinline__ void cp16(uint32_t s, const void* g) {
    asm volatile("cp.async.cg.shared.global [%0], [%1], 16;" :: "r"(s), "l"(g));
}
__device__ __forceinline__ void cp_commit() { asm volatile("cp.async.commit_group;"); }
template <int N> __device__ __forceinline__ void cp_wait() {
    asm volatile("cp.async.wait_group %0;" :: "n"(N));
}
__device__ __forceinline__ void ldsm4(uint32_t* r, uint32_t a) {
    asm volatile("ldmatrix.sync.aligned.m8n8.x4.shared.b16 {%0,%1,%2,%3}, [%4];"
                 : "=r"(r[0]), "=r"(r[1]), "=r"(r[2]), "=r"(r[3]) : "r"(a));
}
__device__ __forceinline__ void ldsm2(uint32_t* r, uint32_t a) {
    asm volatile("ldmatrix.sync.aligned.m8n8.x2.shared.b16 {%0,%1}, [%2];"
                 : "=r"(r[0]), "=r"(r[1]) : "r"(a));
}
__device__ __forceinline__ void mma16816(float* d, const uint32_t* a, const uint32_t* b) {
    asm volatile("mma.sync.aligned.m16n8k16.row.col.f32.f16.f16.f32 "
                 "{%0,%1,%2,%3}, {%4,%5,%6,%7}, {%8,%9}, {%0,%1,%2,%3};"
                 : "+f"(d[0]), "+f"(d[1]), "+f"(d[2]), "+f"(d[3])
                 : "r"(a[0]), "r"(a[1]), "r"(a[2]), "r"(a[3]),
                   "r"(b[0]), "r"(b[1]));
}
__device__ __forceinline__ uint32_t packh2(float a, float b) {
    const __half2 h = __floats2half2_rn(a, b);
    return *reinterpret_cast<const uint32_t*>(&h);
}

// tile-row swizzle: 16B chunk c of row r -> chunk c ^ ((r ^ (r>>2)) & 3)
__device__ __forceinline__ uint32_t swz(int r, int c) {
    return (uint32_t)(r * 64 + ((c ^ ((r ^ (r >> 2)) & 3)) << 4));
}

// ---------------------------------------------------------------------------
// fp16 HMMA GEMM: C[m,n] = sum_k A[m,k]*B[n,k] (both K-major), fp32 accum.
// CTA 128x128, 8 warps (2m x 4n) of 64x32 warp tiles, BK=32, 4-stage cp.async.
// ---------------------------------------------------------------------------
#define NSTAGES 4
#define STAGE_BYTES 16384     // A 8KB + B 8KB
#define SMEMSZ (NSTAGES * STAGE_BYTES)

enum { EPI_SCORES = 0, EPI_PROJ = 1, EPI_ATT = 2, EPI_FC = 3 };

template <int EPI>
__global__ void __launch_bounds__(256, 2)
gemmh(const fp16* __restrict__ A0, const fp16* __restrict__ B0,
      float* __restrict__ Cf, fp16* __restrict__ Ch,
      const float* __restrict__ resid,
      int K, long long strideA, long long strideB, float scale)
{
    extern __shared__ __align__(128) char smem[];
    const uint32_t sb = smem_u32(smem);
    const int tid  = threadIdx.x;
    const int wid  = tid >> 5;
    const int lane = tid & 31;
    const int wm = wid & 1;          // 2 m-groups of 64
    const int wn = wid >> 1;         // 4 n-groups of 32
    const int m0 = blockIdx.y * 128;
    const int n0 = blockIdx.x * 128;
    const int z  = blockIdx.z;

    const fp16* A = A0 + (size_t)z * strideA;
    const fp16* B = B0 + (size_t)z * strideB;

    const int NK = K >> 5;

    auto load_iter = [&](int t, int stage) {
        const uint32_t sA = sb + (uint32_t)stage * STAGE_BYTES;
        const uint32_t sB = sA + 8192;
        const int kb = t * 32;
#pragma unroll
        for (int i = 0; i < 2; i++) {
            const int chunk = i * 256 + tid;   // 512 chunks: 128 rows x 4
            const int r = chunk >> 2, c = chunk & 3;
            cp16(sA + swz(r, c), A + (size_t)(m0 + r) * K + kb + c * 8);
        }
#pragma unroll
        for (int i = 0; i < 2; i++) {
            const int chunk = i * 256 + tid;
            const int r = chunk >> 2, c = chunk & 3;
            cp16(sB + swz(r, c), B + (size_t)(n0 + r) * K + kb + c * 8);
        }
    };

    float acc[4][4][4];
#pragma unroll
    for (int a = 0; a < 4; a++)
#pragma unroll
        for (int b = 0; b < 4; b++)
#pragma unroll
            for (int c = 0; c < 4; c++) acc[a][b][c] = 0.0f;

    load_iter(0, 0); cp_commit();
    load_iter(1, 1); cp_commit();
    load_iter(2, 2); cp_commit();

    for (int i = 0; i < NK; i++) {
        cp_wait<2>();
        __syncthreads();
        const uint32_t sA = sb + (uint32_t)(i & 3) * STAGE_BYTES;
        const uint32_t sB = sA + 8192;

#pragma unroll
        for (int q = 0; q < 2; q++) {
            uint32_t bfr[4][2];
#pragma unroll
            for (int ni = 0; ni < 4; ni++) {
                const int nr = wn * 32 + ni * 8 + (lane & 7);
                const int c  = q * 2 + ((lane >> 3) & 1);
                ldsm2(bfr[ni], sB + swz(nr, c));
            }
#pragma unroll
            for (int mi = 0; mi < 4; mi++) {
                uint32_t afr[4];
                const int mr = wm * 64 + mi * 16 + (lane & 15);
                const int c  = q * 2 + (lane >> 4);
                ldsm4(afr, sA + swz(mr, c));
#pragma unroll
                for (int ni = 0; ni < 4; ni++)
                    mma16816(acc[mi][ni], afr, bfr[ni]);
            }
        }

        const int j = i + 3;
        if (j < NK) load_iter(j, j & 3);
        cp_commit();
    }

    // ---------------- epilogue ----------------
    const int l4 = lane >> 2;            // row within 8
    const int l2 = (lane & 3) * 2;       // col pair
#pragma unroll
    for (int mi = 0; mi < 4; mi++) {
#pragma unroll
        for (int h2 = 0; h2 < 2; h2++) {
            const int row = m0 + wm * 64 + mi * 16 + l4 + h2 * 8;
#pragma unroll
            for (int ni = 0; ni < 4; ni++) {
                const int col = n0 + wn * 32 + ni * 8 + l2;
                const float v0 = acc[mi][ni][2 * h2 + 0];
                const float v1 = acc[mi][ni][2 * h2 + 1];

                if constexpr (EPI == EPI_SCORES) {
                    float* p = Cf + (size_t)z * S_ * S_ + (size_t)row * S_ + col;
                    *reinterpret_cast<float2*>(p) = make_float2(v0 * scale, v1 * scale);
                } else if constexpr (EPI == EPI_FC) {
                    const size_t base = (size_t)row * D_ + col;
                    const float2 rv = *reinterpret_cast<const float2*>(resid + base);
                    *reinterpret_cast<float2*>(Cf + base) =
                        make_float2(v0 + rv.x, v1 + rv.y);
                } else if constexpr (EPI == EPI_PROJ) {
                    const int b = row >> 10, s = row & (S_ - 1);
                    const int hh = col >> 9, d = col & (DK_ - 1);
                    const size_t base = (((size_t)(b * H_ + hh)) * S_ + s) * DK_ + d;
                    *reinterpret_cast<uint32_t*>(Ch + base) = packh2(v0, v1);
                } else { // EPI_ATT
                    const int b = z >> 3, hh = z & (H_ - 1);
                    const size_t base = ((size_t)(b * S_ + row)) * HD_ + hh * DK_ + col;
                    *reinterpret_cast<uint32_t*>(Ch + base) = packh2(v0, v1);
                }
            }
        }
    }
}

// ---------------- fp32 -> fp16 convert ----------------
__global__ void __launch_bounds__(256) conv_k(const float* __restrict__ s,
                                              fp16* __restrict__ h, int n)
{
    const int i = (blockIdx.x * 256 + threadIdx.x) * 4;
    if (i >= n) return;
    float4 v = *reinterpret_cast<const float4*>(s + i);
    *reinterpret_cast<uint2*>(h + i) = make_uint2(packh2(v.x, v.y), packh2(v.z, v.w));
}

// ---------------- V transpose: (z, s, d) -> (z, d, s), 64x64 tiles ----------
__global__ void __launch_bounds__(256) transp_k(const fp16* __restrict__ in,
                                                fp16* __restrict__ out)
{
    __shared__ fp16 t[64][72];
    const int zz = blockIdx.z;
    const int d0 = blockIdx.x * 64, s0 = blockIdx.y * 64;
    const int tid = threadIdx.x;
    const int rs = tid >> 2, cb = (tid & 3) * 16;

    const fp16* src = in + ((size_t)zz * S_ + s0 + rs) * DK_ + d0 + cb;
    *reinterpret_cast<uint4*>(&t[rs][cb])     = reinterpret_cast<const uint4*>(src)[0];
    *reinterpret_cast<uint4*>(&t[rs][cb + 8]) = reinterpret_cast<const uint4*>(src)[1];
    __syncthreads();

    fp16 buf[16];
#pragma unroll
    for (int j = 0; j < 16; j++) buf[j] = t[cb + j][rs];
    fp16* dst = out + ((size_t)zz * DK_ + d0 + rs) * S_ + s0 + cb;
    reinterpret_cast<uint4*>(dst)[0] = *reinterpret_cast<uint4*>(&buf[0]);
    reinterpret_cast<uint4*>(dst)[1] = *reinterpret_cast<uint4*>(&buf[8]);
}

// ---------------- row softmax (len 1024) -> fp16 probs ----------------
__global__ void __launch_bounds__(256) softmax_k(const float* __restrict__ sc,
                                                 fp16* __restrict__ ph)
{
    const size_t row = blockIdx.x;
    const float4* p = reinterpret_cast<const float4*>(sc) + row * 256 + threadIdx.x;
    float4 v = *p;

    __shared__ float red[8];

    float m = fmaxf(fmaxf(v.x, v.y), fmaxf(v.z, v.w));
#pragma unroll
    for (int o = 16; o; o >>= 1) m = fmaxf(m, __shfl_xor_sync(0xffffffffu, m, o));
    if ((threadIdx.x & 31) == 0) red[threadIdx.x >> 5] = m;
    __syncthreads();
    m = red[0];
#pragma unroll
    for (int i = 1; i < 8; i++) m = fmaxf(m, red[i]);

    v.x = expf(v.x - m); v.y = expf(v.y - m);
    v.z = expf(v.z - m); v.w = expf(v.w - m);

    float s = v.x + v.y + v.z + v.w;
#pragma unroll
    for (int o = 16; o; o >>= 1) s += __shfl_xor_sync(0xffffffffu, s, o);
    __syncthreads();
    if ((threadIdx.x & 31) == 0) red[threadIdx.x >> 5] = s;
    __syncthreads();
    s = 0.0f;
#pragma unroll
    for (int i = 0; i < 8; i++) s += red[i];

    const float inv = 1.0f / s;
    const size_t base = row * 1024 + threadIdx.x * 4;
    *reinterpret_cast<uint2*>(ph + base) =
        make_uint2(packh2(v.x * inv, v.y * inv), packh2(v.z * inv, v.w * inv));
}

// ---------------- LayerNorm (len 512), in-place ----------------
__global__ void __launch_bounds__(256) ln_k(float* __restrict__ out,
                                            const float* __restrict__ gamma,
                                            const float* __restrict__ beta)
{
    const size_t row = blockIdx.x;
    float2* p = reinterpret_cast<float2*>(out) + row * 256 + threadIdx.x;
    float2 v = *p;

    float s  = v.x + v.y;
    float ss = v.x * v.x + v.y * v.y;

    __shared__ float r1[8], r2[8];
#pragma unroll
    for (int o = 16; o; o >>= 1) {
        s  += __shfl_xor_sync(0xffffffffu, s, o);
        ss += __shfl_xor_sync(0xffffffffu, ss, o);
    }
    if ((threadIdx.x & 31) == 0) { r1[threadIdx.x >> 5] = s; r2[threadIdx.x >> 5] = ss; }
    __syncthreads();
    s = 0.0f; ss = 0.0f;
#pragma unroll
    for (int i = 0; i < 8; i++) { s += r1[i]; ss += r2[i]; }

    const float mu  = s * (1.0f / 512.0f);
    const float var = ss * (1.0f / 512.0f) - mu * mu;
    const float inv = rsqrtf(var + 1e-6f);

    const int c = threadIdx.x * 2;
    v.x = (v.x - mu) * inv * gamma[c + 0] + beta[c + 0];
    v.y = (v.y - mu) * inv * gamma[c + 1] + beta[c + 1];
    *p = v;
}

// ---------------------------------------------------------------------------
extern "C" void kernel_launch(void* const* d_in, const int* in_sizes, int n_in,
                              void* d_out, int out_size)
{
    const float* in_q  = (const float*)d_in[0];
    const float* in_k  = (const float*)d_in[1];
    const float* in_v  = (const float*)d_in[2];
    const float* w_q   = (const float*)d_in[3];
    const float* w_k   = (const float*)d_in[4];
    const float* w_v   = (const float*)d_in[5];
    const float* w_fc  = (const float*)d_in[6];
    const float* gamma = (const float*)d_in[7];
    const float* beta  = (const float*)d_in[8];
    float* out = (float*)d_out;

    cudaFuncSetAttribute(gemmh<EPI_SCORES>, cudaFuncAttributeMaxDynamicSharedMemorySize, SMEMSZ);
    cudaFuncSetAttribute(gemmh<EPI_PROJ>,   cudaFuncAttributeMaxDynamicSharedMemorySize, SMEMSZ);
    cudaFuncSetAttribute(gemmh<EPI_ATT>,    cudaFuncAttributeMaxDynamicSharedMemorySize, SMEMSZ);
    cudaFuncSetAttribute(gemmh<EPI_FC>,     cudaFuncAttributeMaxDynamicSharedMemorySize, SMEMSZ);

    fp16 *qh, *kh, *vh, *wq, *wk, *wv, *wf;
    fp16 *qhh, *khh, *vhh, *vt, *ph, *at;
    float *sc;
    cudaGetSymbolAddress((void**)&sc, g_sc);
    cudaGetSymbolAddress((void**)&qh, g_q);   cudaGetSymbolAddress((void**)&kh, g_k);
    cudaGetSymbolAddress((void**)&vh, g_v);
    cudaGetSymbolAddress((void**)&wq, g_wq);  cudaGetSymbolAddress((void**)&wk, g_wk);
    cudaGetSymbolAddress((void**)&wv, g_wv);  cudaGetSymbolAddress((void**)&wf, g_wf);
    cudaGetSymbolAddress((void**)&qhh, g_qh); cudaGetSymbolAddress((void**)&khh, g_kh);
    cudaGetSymbolAddress((void**)&vhh, g_vh); cudaGetSymbolAddress((void**)&vt, g_vt);
    cudaGetSymbolAddress((void**)&ph, g_p);   cudaGetSymbolAddress((void**)&at, g_at);

    const int NX = B_ * S_ * D_;     // 4M
    const int NW = HD_ * D_;         // 2M
    conv_k<<<NX / 1024, 256>>>(in_q, qh, NX);
    conv_k<<<NX / 1024, 256>>>(in_k, kh, NX);
    conv_k<<<NX / 1024, 256>>>(in_v, vh, NX);
    conv_k<<<NW / 1024, 256>>>(w_q, wq, NW);
    conv_k<<<NW / 1024, 256>>>(w_k, wk, NW);
    conv_k<<<NW / 1024, 256>>>(w_v, wv, NW);
    conv_k<<<NW / 1024, 256>>>(w_fc, wf, NW);

    const float SCALE = 0.044194173824159216f;   // 1/sqrt(512)

    // 1) projections (M=8192, N=4096, K=512) -> heads layout
    const dim3 gp(HD_ / 128, (B_ * S_) / 128, 1);
    gemmh<EPI_PROJ><<<gp, 256, SMEMSZ>>>(qh, wq, nullptr, qhh, nullptr, D_, 0, 0, 1.0f);
    gemmh<EPI_PROJ><<<gp, 256, SMEMSZ>>>(kh, wk, nullptr, khh, nullptr, D_, 0, 0, 1.0f);
    gemmh<EPI_PROJ><<<gp, 256, SMEMSZ>>>(vh, wv, nullptr, vhh, nullptr, D_, 0, 0, 1.0f);

    // 1b) V transpose: (z,s,d) -> (z,d,s) so PV stays row.col
    transp_k<<<dim3(DK_ / 64, S_ / 64, B_ * H_), 256>>>(vhh, vt);

    // 2) scores (per z: M=N=1024, K=512), scaled
    const dim3 gs(S_ / 128, S_ / 128, B_ * H_);
    gemmh<EPI_SCORES><<<gs, 256, SMEMSZ>>>(qhh, khh, sc, nullptr, nullptr,
                                           DK_, (long long)S_ * DK_, (long long)S_ * DK_, SCALE);

    // 3) softmax -> fp16 P
    softmax_k<<<B_ * H_ * S_, 256>>>(sc, ph);

    // 4) P @ V (per z: M=1024, N=512, K=1024; B = V^T)
    const dim3 gv(DK_ / 128, S_ / 128, B_ * H_);
    gemmh<EPI_ATT><<<gv, 256, SMEMSZ>>>(ph, vt, nullptr, at, nullptr,
                                        S_, (long long)S_ * S_, (long long)DK_ * S_, 1.0f);

    // 5) fc + residual (M=8192, N=512, K=4096)
    const dim3 gf(D_ / 128, (B_ * S_) / 128, 1);
    gemmh<EPI_FC><<<gf, 256, SMEMSZ>>>(at, wf, out, nullptr, in_q, HD_, 0, 0, 1.0f);

    // 6) LayerNorm
    ln_k<<<B_ * S_, 256>>>(out, gamma, beta);
}

// round 7
// speedup vs baseline: 7.9615x; 1.0932x over previous
#include <cuda_runtime.h>
#include <cuda_fp16.h>
#include <cstdint>
#include <cstddef>

#define B_    8
#define S_    1024
#define D_    512
#define H_    8
#define DK_   512
#define HD_   4096

typedef __half fp16;

// ---------------- scratch (device globals; no runtime alloc) ----------------
__device__ fp16 g_sc [(size_t)B_*H_*S_*S_];           // fp16 scaled scores

__device__ fp16 g_q  [(size_t)B_*S_*D_];
__device__ fp16 g_k  [(size_t)B_*S_*D_];
__device__ fp16 g_v  [(size_t)B_*S_*D_];
__device__ fp16 g_wq [(size_t)HD_*D_];
__device__ fp16 g_wk [(size_t)HD_*D_];
__device__ fp16 g_wv [(size_t)HD_*D_];
__device__ fp16 g_wf [(size_t)D_*HD_];

__device__ fp16 g_qh [(size_t)B_*H_*S_*DK_];
__device__ fp16 g_kh [(size_t)B_*H_*S_*DK_];
__device__ fp16 g_vh [(size_t)B_*H_*S_*DK_];          // V heads (z, s, d)
__device__ fp16 g_vt [(size_t)B_*H_*DK_*S_];          // V transposed (z, d, s)
__device__ fp16 g_p  [(size_t)B_*H_*S_*S_];           // softmax probs
__device__ fp16 g_at [(size_t)B_*S_*HD_];             // attention output

// ---------------- helpers ----------------
__device__ __forceinline__ uint32_t smem_u32(const void* p) {
    uint32_t a;
    asm("{ .reg .u64 t; cvta.to.shared.u64 t, %1; cvt.u32.u64 %0, t; }"
        : "=r"(a) : "l"(p));
    return a;
}
__device__ __forceinline__ void cp16(uint32_t s, const void* g) {
    asm volatile("cp.async.cg.shared.global [%0], [%1], 16;" :: "r"(s), "l"(g));
}
__device__ __forceinline__ void cp_commit() { asm volatile("cp.async.commit_group;"); }
template <int N> __device__ __forceinline__ void cp_wait() {
    asm volatile("cp.async.wait_group %0;" :: "n"(N));
}
__device__ __forceinline__ void ldsm4(uint32_t* r, uint32_t a) {
    asm volatile("ldmatrix.sync.aligned.m8n8.x4.shared.b16 {%0,%1,%2,%3}, [%4];"
                 : "=r"(r[0]), "=r"(r[1]), "=r"(r[2]), "=r"(r[3]) : "r"(a));
}
__device__ __forceinline__ void ldsm2(uint32_t* r, uint32_t a) {
    asm volatile("ldmatrix.sync.aligned.m8n8.x2.shared.b16 {%0,%1}, [%2];"
                 : "=r"(r[0]), "=r"(r[1]) : "r"(a));
}
__device__ __forceinline__ void mma16816(float* d, const uint32_t* a, const uint32_t* b) {
    asm volatile("mma.sync.aligned.m16n8k16.row.col.f32.f16.f16.f32 "
                 "{%0,%1,%2,%3}, {%4,%5,%6,%7}, {%8,%9}, {%0,%1,%2,%3};"
                 : "+f"(d[0]), "+f"(d[1]), "+f"(d[2]), "+f"(d[3])
                 : "r"(a[0]), "r"(a[1]), "r"(a[2]), "r"(a[3]),
                   "r"(b[0]), "r"(b[1]));
}
__device__ __forceinline__ uint32_t packh2(float a, float b) {
    const __half2 h = __floats2half2_rn(a, b);
    return *reinterpret_cast<const uint32_t*>(&h);
}

// tile-row swizzle: 16B chunk c of row r -> chunk c ^ ((r ^ (r>>2)) & 3)
__device__ __forceinline__ uint32_t swz(int r, int c) {
    return (uint32_t)(r * 64 + ((c ^ ((r ^ (r >> 2)) & 3)) << 4));
}

// ---------------------------------------------------------------------------
// fp16 HMMA GEMM: C[m,n] = sum_k A[m,k]*B[n,k] (both K-major), fp32 accum.
// CTA 128x128, 4 warps (2m x 2n) of 64x64 warp tiles, BK=32, 4-stage cp.async.
// Smem reads per iter: A 8KB*2 + B 8KB*2 = 32KB for 524K MACs (16 MAC/B).
// ---------------------------------------------------------------------------
#define NSTAGES 4
#define STAGE_BYTES 16384     // A 8KB + B 8KB
#define SMEMSZ (NSTAGES * STAGE_BYTES)

enum { EPI_SCORES = 0, EPI_PROJ = 1, EPI_ATT = 2, EPI_FC = 3 };

template <int EPI>
__global__ void __launch_bounds__(128, 2)
gemmh(const fp16* __restrict__ A0, const fp16* __restrict__ B0,
      float* __restrict__ Cf, fp16* __restrict__ Ch,
      const float* __restrict__ resid,
      int K, long long strideA, long long strideB, float scale)
{
    extern __shared__ __align__(128) char smem[];
    const uint32_t sb = smem_u32(smem);
    const int tid  = threadIdx.x;
    const int wid  = tid >> 5;
    const int lane = tid & 31;
    const int wm = wid & 1;          // 2 m-groups of 64
    const int wn = wid >> 1;         // 2 n-groups of 64
    const int m0 = blockIdx.y * 128;
    const int n0 = blockIdx.x * 128;
    const int z  = blockIdx.z;

    const fp16* A = A0 + (size_t)z * strideA;
    const fp16* B = B0 + (size_t)z * strideB;

    const int NK = K >> 5;

    auto load_iter = [&](int t, int stage) {
        const uint32_t sA = sb + (uint32_t)stage * STAGE_BYTES;
        const uint32_t sB = sA + 8192;
        const int kb = t * 32;
#pragma unroll
        for (int i = 0; i < 4; i++) {
            const int chunk = i * 128 + tid;   // 512 chunks: 128 rows x 4
            const int r = chunk >> 2, c = chunk & 3;
            cp16(sA + swz(r, c), A + (size_t)(m0 + r) * K + kb + c * 8);
        }
#pragma unroll
        for (int i = 0; i < 4; i++) {
            const int chunk = i * 128 + tid;
            const int r = chunk >> 2, c = chunk & 3;
            cp16(sB + swz(r, c), B + (size_t)(n0 + r) * K + kb + c * 8);
        }
    };

    float acc[4][8][4];
#pragma unroll
    for (int a = 0; a < 4; a++)
#pragma unroll
        for (int b = 0; b < 8; b++)
#pragma unroll
            for (int c = 0; c < 4; c++) acc[a][b][c] = 0.0f;

    load_iter(0, 0); cp_commit();
    load_iter(1, 1); cp_commit();
    load_iter(2, 2); cp_commit();

    for (int i = 0; i < NK; i++) {
        cp_wait<2>();
        __syncthreads();
        const uint32_t sA = sb + (uint32_t)(i & 3) * STAGE_BYTES;
        const uint32_t sB = sA + 8192;

#pragma unroll
        for (int q = 0; q < 2; q++) {
            uint32_t bfr[8][2];
#pragma unroll
            for (int ni = 0; ni < 8; ni++) {
                const int nr = wn * 64 + ni * 8 + (lane & 7);
                const int c  = q * 2 + ((lane >> 3) & 1);
                ldsm2(bfr[ni], sB + swz(nr, c));
            }
#pragma unroll
            for (int mi = 0; mi < 4; mi++) {
                uint32_t afr[4];
                const int mr = wm * 64 + mi * 16 + (lane & 15);
                const int c  = q * 2 + (lane >> 4);
                ldsm4(afr, sA + swz(mr, c));
#pragma unroll
                for (int ni = 0; ni < 8; ni++)
                    mma16816(acc[mi][ni], afr, bfr[ni]);
            }
        }

        const int j = i + 3;
        if (j < NK) load_iter(j, j & 3);
        cp_commit();
    }

    // ---------------- epilogue ----------------
    const int l4 = lane >> 2;            // row within 8
    const int l2 = (lane & 3) * 2;       // col pair
#pragma unroll
    for (int mi = 0; mi < 4; mi++) {
#pragma unroll
        for (int h2 = 0; h2 < 2; h2++) {
            const int row = m0 + wm * 64 + mi * 16 + l4 + h2 * 8;
#pragma unroll
            for (int ni = 0; ni < 8; ni++) {
                const int col = n0 + wn * 64 + ni * 8 + l2;
                const float v0 = acc[mi][ni][2 * h2 + 0];
                const float v1 = acc[mi][ni][2 * h2 + 1];

                if constexpr (EPI == EPI_SCORES) {
                    fp16* p = Ch + (size_t)z * S_ * S_ + (size_t)row * S_ + col;
                    *reinterpret_cast<uint32_t*>(p) = packh2(v0 * scale, v1 * scale);
                } else if constexpr (EPI == EPI_FC) {
                    const size_t base = (size_t)row * D_ + col;
                    const float2 rv = *reinterpret_cast<const float2*>(resid + base);
                    *reinterpret_cast<float2*>(Cf + base) =
                        make_float2(v0 + rv.x, v1 + rv.y);
                } else if constexpr (EPI == EPI_PROJ) {
                    const int b = row >> 10, s = row & (S_ - 1);
                    const int hh = col >> 9, d = col & (DK_ - 1);
                    const size_t base = (((size_t)(b * H_ + hh)) * S_ + s) * DK_ + d;
                    *reinterpret_cast<uint32_t*>(Ch + base) = packh2(v0, v1);
                } else { // EPI_ATT
                    const int b = z >> 3, hh = z & (H_ - 1);
                    const size_t base = ((size_t)(b * S_ + row)) * HD_ + hh * DK_ + col;
                    *reinterpret_cast<uint32_t*>(Ch + base) = packh2(v0, v1);
                }
            }
        }
    }
}

// ---------------- fp32 -> fp16 convert (multi-tensor via blockIdx.z) --------
__global__ void __launch_bounds__(256) conv3_k(const float* __restrict__ s0,
                                               const float* __restrict__ s1,
                                               const float* __restrict__ s2,
                                               fp16* __restrict__ h0,
                                               fp16* __restrict__ h1,
                                               fp16* __restrict__ h2, int n)
{
    const float* s = (blockIdx.z == 0) ? s0 : (blockIdx.z == 1) ? s1 : s2;
    fp16*       h = (blockIdx.z == 0) ? h0 : (blockIdx.z == 1) ? h1 : h2;
    const int i = (blockIdx.x * 256 + threadIdx.x) * 4;
    if (i >= n) return;
    float4 v = *reinterpret_cast<const float4*>(s + i);
    *reinterpret_cast<uint2*>(h + i) = make_uint2(packh2(v.x, v.y), packh2(v.z, v.w));
}

__global__ void __launch_bounds__(256) conv4_k(const float* __restrict__ s0,
                                               const float* __restrict__ s1,
                                               const float* __restrict__ s2,
                                               const float* __restrict__ s3,
                                               fp16* __restrict__ h0,
                                               fp16* __restrict__ h1,
                                               fp16* __restrict__ h2,
                                               fp16* __restrict__ h3, int n)
{
    const float* s = (blockIdx.z == 0) ? s0 : (blockIdx.z == 1) ? s1
                   : (blockIdx.z == 2) ? s2 : s3;
    fp16*       h = (blockIdx.z == 0) ? h0 : (blockIdx.z == 1) ? h1
                   : (blockIdx.z == 2) ? h2 : h3;
    const int i = (blockIdx.x * 256 + threadIdx.x) * 4;
    if (i >= n) return;
    float4 v = *reinterpret_cast<const float4*>(s + i);
    *reinterpret_cast<uint2*>(h + i) = make_uint2(packh2(v.x, v.y), packh2(v.z, v.w));
}

// ---------------- V transpose: (z, s, d) -> (z, d, s), 64x64 tiles ----------
__global__ void __launch_bounds__(256) transp_k(const fp16* __restrict__ in,
                                                fp16* __restrict__ out)
{
    __shared__ fp16 t[64][72];
    const int zz = blockIdx.z;
    const int d0 = blockIdx.x * 64, s0 = blockIdx.y * 64;
    const int tid = threadIdx.x;
    const int rs = tid >> 2, cb = (tid & 3) * 16;

    const fp16* src = in + ((size_t)zz * S_ + s0 + rs) * DK_ + d0 + cb;
    *reinterpret_cast<uint4*>(&t[rs][cb])     = reinterpret_cast<const uint4*>(src)[0];
    *reinterpret_cast<uint4*>(&t[rs][cb + 8]) = reinterpret_cast<const uint4*>(src)[1];
    __syncthreads();

    fp16 buf[16];
#pragma unroll
    for (int j = 0; j < 16; j++) buf[j] = t[cb + j][rs];
    fp16* dst = out + ((size_t)zz * DK_ + d0 + rs) * S_ + s0 + cb;
    reinterpret_cast<uint4*>(dst)[0] = *reinterpret_cast<uint4*>(&buf[0]);
    reinterpret_cast<uint4*>(dst)[1] = *reinterpret_cast<uint4*>(&buf[8]);
}

// ---------------- row softmax (len 1024, fp16 in) -> fp16 probs -------------
__global__ void __launch_bounds__(256) softmax_k(const fp16* __restrict__ sc,
                                                 fp16* __restrict__ ph)
{
    const size_t row = blockIdx.x;
    const uint2 raw = *(reinterpret_cast<const uint2*>(sc) + row * 256 + threadIdx.x);
    const __half2 h01 = *reinterpret_cast<const __half2*>(&raw.x);
    const __half2 h23 = *reinterpret_cast<const __half2*>(&raw.y);
    const float2 f01 = __half22float2(h01);
    const float2 f23 = __half22float2(h23);
    float4 v = make_float4(f01.x, f01.y, f23.x, f23.y);

    __shared__ float red[8];

    float m = fmaxf(fmaxf(v.x, v.y), fmaxf(v.z, v.w));
#pragma unroll
    for (int o = 16; o; o >>= 1) m = fmaxf(m, __shfl_xor_sync(0xffffffffu, m, o));
    if ((threadIdx.x & 31) == 0) red[threadIdx.x >> 5] = m;
    __syncthreads();
    m = red[0];
#pragma unroll
    for (int i = 1; i < 8; i++) m = fmaxf(m, red[i]);

    v.x = expf(v.x - m); v.y = expf(v.y - m);
    v.z = expf(v.z - m); v.w = expf(v.w - m);

    float s = v.x + v.y + v.z + v.w;
#pragma unroll
    for (int o = 16; o; o >>= 1) s += __shfl_xor_sync(0xffffffffu, s, o);
    __syncthreads();
    if ((threadIdx.x & 31) == 0) red[threadIdx.x >> 5] = s;
    __syncthreads();
    s = 0.0f;
#pragma unroll
    for (int i = 0; i < 8; i++) s += red[i];

    const float inv = 1.0f / s;
    const size_t base = row * 1024 + threadIdx.x * 4;
    *reinterpret_cast<uint2*>(ph + base) =
        make_uint2(packh2(v.x * inv, v.y * inv), packh2(v.z * inv, v.w * inv));
}

// ---------------- LayerNorm (len 512), in-place ----------------
__global__ void __launch_bounds__(256) ln_k(float* __restrict__ out,
                                            const float* __restrict__ gamma,
                                            const float* __restrict__ beta)
{
    const size_t row = blockIdx.x;
    float2* p = reinterpret_cast<float2*>(out) + row * 256 + threadIdx.x;
    float2 v = *p;

    float s  = v.x + v.y;
    float ss = v.x * v.x + v.y * v.y;

    __shared__ float r1[8], r2[8];
#pragma unroll
    for (int o = 16; o; o >>= 1) {
        s  += __shfl_xor_sync(0xffffffffu, s, o);
        ss += __shfl_xor_sync(0xffffffffu, ss, o);
    }
    if ((threadIdx.x & 31) == 0) { r1[threadIdx.x >> 5] = s; r2[threadIdx.x >> 5] = ss; }
    __syncthreads();
    s = 0.0f; ss = 0.0f;
#pragma unroll
    for (int i = 0; i < 8; i++) { s += r1[i]; ss += r2[i]; }

    const float mu  = s * (1.0f / 512.0f);
    const float var = ss * (1.0f / 512.0f) - mu * mu;
    const float inv = rsqrtf(var + 1e-6f);

    const int c = threadIdx.x * 2;
    v.x = (v.x - mu) * inv * gamma[c + 0] + beta[c + 0];
    v.y = (v.y - mu) * inv * gamma[c + 1] + beta[c + 1];
    *p = v;
}

// ---------------------------------------------------------------------------
extern "C" void kernel_launch(void* const* d_in, const int* in_sizes, int n_in,
                              void* d_out, int out_size)
{
    const float* in_q  = (const float*)d_in[0];
    const float* in_k  = (const float*)d_in[1];
    const float* in_v  = (const float*)d_in[2];
    const float* w_q   = (const float*)d_in[3];
    const float* w_k   = (const float*)d_in[4];
    const float* w_v   = (const float*)d_in[5];
    const float* w_fc  = (const float*)d_in[6];
    const float* gamma = (const float*)d_in[7];
    const float* beta  = (const float*)d_in[8];
    float* out = (float*)d_out;

    cudaFuncSetAttribute(gemmh<EPI_SCORES>, cudaFuncAttributeMaxDynamicSharedMemorySize, SMEMSZ);
    cudaFuncSetAttribute(gemmh<EPI_PROJ>,   cudaFuncAttributeMaxDynamicSharedMemorySize, SMEMSZ);
    cudaFuncSetAttribute(gemmh<EPI_ATT>,    cudaFuncAttributeMaxDynamicSharedMemorySize, SMEMSZ);
    cudaFuncSetAttribute(gemmh<EPI_FC>,     cudaFuncAttributeMaxDynamicSharedMemorySize, SMEMSZ);

    fp16 *qh, *kh, *vh, *wq, *wk, *wv, *wf;
    fp16 *qhh, *khh, *vhh, *vt, *ph, *at, *sc;
    cudaGetSymbolAddress((void**)&sc, g_sc);
    cudaGetSymbolAddress((void**)&qh, g_q);   cudaGetSymbolAddress((void**)&kh, g_k);
    cudaGetSymbolAddress((void**)&vh, g_v);
    cudaGetSymbolAddress((void**)&wq, g_wq);  cudaGetSymbolAddress((void**)&wk, g_wk);
    cudaGetSymbolAddress((void**)&wv, g_wv);  cudaGetSymbolAddress((void**)&wf, g_wf);
    cudaGetSymbolAddress((void**)&qhh, g_qh); cudaGetSymbolAddress((void**)&khh, g_kh);
    cudaGetSymbolAddress((void**)&vhh, g_vh); cudaGetSymbolAddress((void**)&vt, g_vt);
    cudaGetSymbolAddress((void**)&ph, g_p);   cudaGetSymbolAddress((void**)&at, g_at);

    const int NX = B_ * S_ * D_;     // 4M
    const int NW = HD_ * D_;         // 2M
    conv3_k<<<dim3(NX / 1024, 1, 3), 256>>>(in_q, in_k, in_v, qh, kh, vh, NX);
    conv4_k<<<dim3(NW / 1024, 1, 4), 256>>>(w_q, w_k, w_v, w_fc, wq, wk, wv, wf, NW);

    const float SCALE = 0.044194173824159216f;   // 1/sqrt(512)

    // 1) projections (M=8192, N=4096, K=512) -> heads layout
    const dim3 gp(HD_ / 128, (B_ * S_) / 128, 1);
    gemmh<EPI_PROJ><<<gp, 128, SMEMSZ>>>(qh, wq, nullptr, qhh, nullptr, D_, 0, 0, 1.0f);
    gemmh<EPI_PROJ><<<gp, 128, SMEMSZ>>>(kh, wk, nullptr, khh, nullptr, D_, 0, 0, 1.0f);
    gemmh<EPI_PROJ><<<gp, 128, SMEMSZ>>>(vh, wv, nullptr, vhh, nullptr, D_, 0, 0, 1.0f);

    // 1b) V transpose: (z,s,d) -> (z,d,s) so PV stays row.col
    transp_k<<<dim3(DK_ / 64, S_ / 64, B_ * H_), 256>>>(vhh, vt);

    // 2) scores (per z: M=N=1024, K=512), scaled, fp16 out
    const dim3 gs(S_ / 128, S_ / 128, B_ * H_);
    gemmh<EPI_SCORES><<<gs, 128, SMEMSZ>>>(qhh, khh, nullptr, sc, nullptr,
                                           DK_, (long long)S_ * DK_, (long long)S_ * DK_, SCALE);

    // 3) softmax -> fp16 P
    softmax_k<<<B_ * H_ * S_, 256>>>(sc, ph);

    // 4) P @ V (per z: M=1024, N=512, K=1024; B = V^T)
    const dim3 gv(DK_ / 128, S_ / 128, B_ * H_);
    gemmh<EPI_ATT><<<gv, 128, SMEMSZ>>>(ph, vt, nullptr, at, nullptr,
                                        S_, (long long)S_ * S_, (long long)DK_ * S_, 1.0f);

    // 5) fc + residual (M=8192, N=512, K=4096)
    const dim3 gf(D_ / 128, (B_ * S_) / 128, 1);
    gemmh<EPI_FC><<<gf, 128, SMEMSZ>>>(at, wf, out, nullptr, in_q, HD_, 0, 0, 1.0f);

    // 6) LayerNorm
    ln_k<<<B_ * S_, 256>>>(out, gamma, beta);
}

// round 9
// speedup vs baseline: 8.1999x; 1.0299x over previous
#include <cuda_runtime.h>
#include <cuda_fp16.h>
#include <cstdint>
#include <cstddef>

#define B_    8
#define S_    1024
#define D_    512
#define H_    8
#define DK_   512
#define HD_   4096

typedef __half fp16;

// ---------------- scratch (device globals; no runtime alloc) ----------------
__device__ fp16 g_sc [(size_t)B_*H_*S_*S_];           // fp16 scaled scores

__device__ fp16 g_q  [(size_t)B_*S_*D_];
__device__ fp16 g_k  [(size_t)B_*S_*D_];
__device__ fp16 g_v  [(size_t)B_*S_*D_];
__device__ fp16 g_wq [(size_t)HD_*D_];
__device__ fp16 g_wk [(size_t)HD_*D_];
__device__ fp16 g_wv [(size_t)HD_*D_];
__device__ fp16 g_wf [(size_t)D_*HD_];

__device__ fp16 g_qh [(size_t)B_*H_*S_*DK_];
__device__ fp16 g_kh [(size_t)B_*H_*S_*DK_];
__device__ fp16 g_vh [(size_t)B_*H_*S_*DK_];          // V heads (z, s, d)
__device__ fp16 g_vt [(size_t)B_*H_*DK_*S_];          // V transposed (z, d, s)
__device__ fp16 g_p  [(size_t)B_*H_*S_*S_];           // softmax probs
__device__ fp16 g_at [(size_t)B_*S_*HD_];             // attention output

// ---------------- helpers ----------------
__device__ __forceinline__ uint32_t smem_u32(const void* p) {
    uint32_t a;
    asm("{ .reg .u64 t; cvta.to.shared.u64 t, %1; cvt.u32.u64 %0, t; }"
        : "=r"(a) : "l"(p));
    return a;
}
__device__ __forceinline__ void cp16(uint32_t s, const void* g) {
    asm volatile("cp.async.cg.shared.global [%0], [%1], 16;" :: "r"(s), "l"(g));
}
__device__ __forceinline__ void cp_commit() { asm volatile("cp.async.commit_group;"); }
template <int N> __device__ __forceinline__ void cp_wait() {
    asm volatile("cp.async.wait_group %0;" :: "n"(N));
}
__device__ __forceinline__ void ldsm4(uint32_t* r, uint32_t a) {
    asm volatile("ldmatrix.sync.aligned.m8n8.x4.shared.b16 {%0,%1,%2,%3}, [%4];"
                 : "=r"(r[0]), "=r"(r[1]), "=r"(r[2]), "=r"(r[3]) : "r"(a));
}
__device__ __forceinline__ void mma16816(float* d, const uint32_t* a, const uint32_t* b) {
    asm volatile("mma.sync.aligned.m16n8k16.row.col.f32.f16.f16.f32 "
                 "{%0,%1,%2,%3}, {%4,%5,%6,%7}, {%8,%9}, {%0,%1,%2,%3};"
                 : "+f"(d[0]), "+f"(d[1]), "+f"(d[2]), "+f"(d[3])
                 : "r"(a[0]), "r"(a[1]), "r"(a[2]), "r"(a[3]),
                   "r"(b[0]), "r"(b[1]));
}
__device__ __forceinline__ uint32_t packh2(float a, float b) {
    const __half2 h = __floats2half2_rn(a, b);
    return *reinterpret_cast<const uint32_t*>(&h);
}

// 128B-row swizzle: 16B chunk c of row r -> chunk c ^ (r & 7)
__device__ __forceinline__ uint32_t swz8(int r, int c) {
    return (uint32_t)(r * 128 + ((c ^ (r & 7)) << 4));
}

// ---------------------------------------------------------------------------
// fp16 HMMA GEMM: C[m,n] = sum_k A[m,k]*B[n,k] (both K-major), fp32 accum.
// CTA 128x128, 4 warps (2m x 2n) of 64x64 tiles, BK=64, 3-stage cp.async.
// ---------------------------------------------------------------------------
#define NSTAGES 3
#define STAGE_BYTES 32768     // A 16KB + B 16KB (128 rows x 128B)
#define SMEMSZ (NSTAGES * STAGE_BYTES)

enum { EPI_SCORES = 0, EPI_PROJ = 1, EPI_ATT = 2, EPI_FC = 3 };

template <int EPI>
__global__ void __launch_bounds__(128, 2)
gemmh(const fp16* __restrict__ A0, const fp16* __restrict__ B0,
      float* __restrict__ Cf, fp16* __restrict__ Ch,
      const float* __restrict__ resid,
      int K, long long strideA, long long strideB, float scale)
{
    extern __shared__ __align__(128) char smem[];
    const uint32_t sb = smem_u32(smem);
    const int tid  = threadIdx.x;
    const int wid  = tid >> 5;
    const int lane = tid & 31;
    const int wm = wid & 1;          // 2 m-groups of 64
    const int wn = wid >> 1;         // 2 n-groups of 64
    const int m0 = blockIdx.y * 128;
    const int n0 = blockIdx.x * 128;
    const int z  = blockIdx.z;

    const fp16* A = A0 + (size_t)z * strideA;
    const fp16* B = B0 + (size_t)z * strideB;

    const int NK = K >> 6;

    auto load_iter = [&](int t, int stage) {
        const uint32_t sA = sb + (uint32_t)stage * STAGE_BYTES;
        const uint32_t sB = sA + 16384;
        const int kb = t * 64;
#pragma unroll
        for (int i = 0; i < 8; i++) {
            const int chunk = i * 128 + tid;   // 1024 chunks: 128 rows x 8
            const int r = chunk >> 3, c = chunk & 7;
            cp16(sA + swz8(r, c), A + (size_t)(m0 + r) * K + kb + c * 8);
        }
#pragma unroll
        for (int i = 0; i < 8; i++) {
            const int chunk = i * 128 + tid;
            const int r = chunk >> 3, c = chunk & 7;
            cp16(sB + swz8(r, c), B + (size_t)(n0 + r) * K + kb + c * 8);
        }
    };

    float acc[4][8][4];
#pragma unroll
    for (int a = 0; a < 4; a++)
#pragma unroll
        for (int b = 0; b < 8; b++)
#pragma unroll
            for (int c = 0; c < 4; c++) acc[a][b][c] = 0.0f;

    load_iter(0, 0); cp_commit();
    load_iter(1, 1); cp_commit();

    const int g  = lane >> 3;              // ldsm4 address-group id
    const int gl = lane & 7;

    for (int i = 0; i < NK; i++) {
        cp_wait<1>();
        __syncthreads();
        const uint32_t sA = sb + (uint32_t)(i % 3) * STAGE_BYTES;
        const uint32_t sB = sA + 16384;

#pragma unroll
        for (int q = 0; q < 4; q++) {
            uint32_t bfr[8][2];
#pragma unroll
            for (int ni = 0; ni < 8; ni += 2) {
                uint32_t r4[4];
                // 4 matrices: (ni,c0),(ni,c1),(ni+1,c0),(ni+1,c1)
                const int nr = wn * 64 + ni * 8 + ((g >> 1) << 3) + gl;
                const int c  = q * 2 + (g & 1);
                ldsm4(r4, sB + swz8(nr, c));
                bfr[ni][0]     = r4[0]; bfr[ni][1]     = r4[1];
                bfr[ni + 1][0] = r4[2]; bfr[ni + 1][1] = r4[3];
            }
#pragma unroll
            for (int mi = 0; mi < 4; mi++) {
                uint32_t afr[4];
                const int mr = wm * 64 + mi * 16 + (lane & 15);
                const int c  = q * 2 + (lane >> 4);
                ldsm4(afr, sA + swz8(mr, c));
#pragma unroll
                for (int ni = 0; ni < 8; ni++)
                    mma16816(acc[mi][ni], afr, bfr[ni]);
            }
        }

        const int j = i + 2;
        if (j < NK) { load_iter(j, j % 3); }
        cp_commit();
    }

    // ---------------- epilogue ----------------
    const int l4 = lane >> 2;            // row within 8
    const int l2 = (lane & 3) * 2;       // col pair
#pragma unroll
    for (int mi = 0; mi < 4; mi++) {
#pragma unroll
        for (int h2 = 0; h2 < 2; h2++) {
            const int row = m0 + wm * 64 + mi * 16 + l4 + h2 * 8;
#pragma unroll
            for (int ni = 0; ni < 8; ni++) {
                const int col = n0 + wn * 64 + ni * 8 + l2;
                const float v0 = acc[mi][ni][2 * h2 + 0];
                const float v1 = acc[mi][ni][2 * h2 + 1];

                if constexpr (EPI == EPI_SCORES) {
                    fp16* p = Ch + (size_t)z * S_ * S_ + (size_t)row * S_ + col;
                    *reinterpret_cast<uint32_t*>(p) = packh2(v0 * scale, v1 * scale);
                } else if constexpr (EPI == EPI_FC) {
                    const size_t base = (size_t)row * D_ + col;
                    const float2 rv = *reinterpret_cast<const float2*>(resid + base);
                    *reinterpret_cast<float2*>(Cf + base) =
                        make_float2(v0 + rv.x, v1 + rv.y);
                } else if constexpr (EPI == EPI_PROJ) {
                    const int b = row >> 10, s = row & (S_ - 1);
                    const int hh = col >> 9, d = col & (DK_ - 1);
                    const size_t base = (((size_t)(b * H_ + hh)) * S_ + s) * DK_ + d;
                    *reinterpret_cast<uint32_t*>(Ch + base) = packh2(v0, v1);
                } else { // EPI_ATT
                    const int b = z >> 3, hh = z & (H_ - 1);
                    const size_t base = ((size_t)(b * S_ + row)) * HD_ + hh * DK_ + col;
                    *reinterpret_cast<uint32_t*>(Ch + base) = packh2(v0, v1);
                }
            }
        }
    }
}

// ---------------- fp32 -> fp16 convert (multi-tensor via blockIdx.z) --------
__global__ void __launch_bounds__(256) conv3_k(const float* __restrict__ s0,
                                               const float* __restrict__ s1,
                                               const float* __restrict__ s2,
                                               fp16* __restrict__ h0,
                                               fp16* __restrict__ h1,
                                               fp16* __restrict__ h2, int n)
{
    const float* s = (blockIdx.z == 0) ? s0 : (blockIdx.z == 1) ? s1 : s2;
    fp16*       h = (blockIdx.z == 0) ? h0 : (blockIdx.z == 1) ? h1 : h2;
    const int i = (blockIdx.x * 256 + threadIdx.x) * 4;
    if (i >= n) return;
    float4 v = *reinterpret_cast<const float4*>(s + i);
    *reinterpret_cast<uint2*>(h + i) = make_uint2(packh2(v.x, v.y), packh2(v.z, v.w));
}

__global__ void __launch_bounds__(256) conv4_k(const float* __restrict__ s0,
                                               const float* __restrict__ s1,
                                               const float* __restrict__ s2,
                                               const float* __restrict__ s3,
                                               fp16* __restrict__ h0,
                                               fp16* __restrict__ h1,
                                               fp16* __restrict__ h2,
                                               fp16* __restrict__ h3, int n)
{
    const float* s = (blockIdx.z == 0) ? s0 : (blockIdx.z == 1) ? s1
                   : (blockIdx.z == 2) ? s2 : s3;
    fp16*       h = (blockIdx.z == 0) ? h0 : (blockIdx.z == 1) ? h1
                   : (blockIdx.z == 2) ? h2 : h3;
    const int i = (blockIdx.x * 256 + threadIdx.x) * 4;
    if (i >= n) return;
    float4 v = *reinterpret_cast<const float4*>(s + i);
    *reinterpret_cast<uint2*>(h + i) = make_uint2(packh2(v.x, v.y), packh2(v.z, v.w));
}

// ---------------- V transpose: (z, s, d) -> (z, d, s), 64x64 tiles ----------
__global__ void __launch_bounds__(256) transp_k(const fp16* __restrict__ in,
                                                fp16* __restrict__ out)
{
    __shared__ fp16 t[64][72];
    const int zz = blockIdx.z;
    const int d0 = blockIdx.x * 64, s0 = blockIdx.y * 64;
    const int tid = threadIdx.x;
    const int rs = tid >> 2, cb = (tid & 3) * 16;

    const fp16* src = in + ((size_t)zz * S_ + s0 + rs) * DK_ + d0 + cb;
    *reinterpret_cast<uint4*>(&t[rs][cb])     = reinterpret_cast<const uint4*>(src)[0];
    *reinterpret_cast<uint4*>(&t[rs][cb + 8]) = reinterpret_cast<const uint4*>(src)[1];
    __syncthreads();

    fp16 buf[16];
#pragma unroll
    for (int j = 0; j < 16; j++) buf[j] = t[cb + j][rs];
    fp16* dst = out + ((size_t)zz * DK_ + d0 + rs) * S_ + s0 + cb;
    reinterpret_cast<uint4*>(dst)[0] = *reinterpret_cast<uint4*>(&buf[0]);
    reinterpret_cast<uint4*>(dst)[1] = *reinterpret_cast<uint4*>(&buf[8]);
}

// ---------------- row softmax (len 1024, fp16 in) -> fp16 probs -------------
__global__ void __launch_bounds__(256) softmax_k(const fp16* __restrict__ sc,
                                                 fp16* __restrict__ ph)
{
    const size_t row = blockIdx.x;
    const uint2 raw = *(reinterpret_cast<const uint2*>(sc) + row * 256 + threadIdx.x);
    const __half2 h01 = *reinterpret_cast<const __half2*>(&raw.x);
    const __half2 h23 = *reinterpret_cast<const __half2*>(&raw.y);
    const float2 f01 = __half22float2(h01);
    const float2 f23 = __half22float2(h23);
    float4 v = make_float4(f01.x, f01.y, f23.x, f23.y);

    __shared__ float red[8];

    float m = fmaxf(fmaxf(v.x, v.y), fmaxf(v.z, v.w));
#pragma unroll
    for (int o = 16; o; o >>= 1) m = fmaxf(m, __shfl_xor_sync(0xffffffffu, m, o));
    if ((threadIdx.x & 31) == 0) red[threadIdx.x >> 5] = m;
    __syncthreads();
    m = red[0];
#pragma unroll
    for (int i = 1; i < 8; i++) m = fmaxf(m, red[i]);

    v.x = expf(v.x - m); v.y = expf(v.y - m);
    v.z = expf(v.z - m); v.w = expf(v.w - m);

    float s = v.x + v.y + v.z + v.w;
#pragma unroll
    for (int o = 16; o; o >>= 1) s += __shfl_xor_sync(0xffffffffu, s, o);
    __syncthreads();
    if ((threadIdx.x & 31) == 0) red[threadIdx.x >> 5] = s;
    __syncthreads();
    s = 0.0f;
#pragma unroll
    for (int i = 0; i < 8; i++) s += red[i];

    const float inv = 1.0f / s;
    const size_t base = row * 1024 + threadIdx.x * 4;
    *reinterpret_cast<uint2*>(ph + base) =
        make_uint2(packh2(v.x * inv, v.y * inv), packh2(v.z * inv, v.w * inv));
}

// ---------------- LayerNorm (len 512), in-place ----------------
__global__ void __launch_bounds__(256) ln_k(float* __restrict__ out,
                                            const float* __restrict__ gamma,
                                            const float* __restrict__ beta)
{
    const size_t row = blockIdx.x;
    float2* p = reinterpret_cast<float2*>(out) + row * 256 + threadIdx.x;
    float2 v = *p;

    float s  = v.x + v.y;
    float ss = v.x * v.x + v.y * v.y;

    __shared__ float r1[8], r2[8];
#pragma unroll
    for (int o = 16; o; o >>= 1) {
        s  += __shfl_xor_sync(0xffffffffu, s, o);
        ss += __shfl_xor_sync(0xffffffffu, ss, o);
    }
    if ((threadIdx.x & 31) == 0) { r1[threadIdx.x >> 5] = s; r2[threadIdx.x >> 5] = ss; }
    __syncthreads();
    s = 0.0f; ss = 0.0f;
#pragma unroll
    for (int i = 0; i < 8; i++) { s += r1[i]; ss += r2[i]; }

    const float mu  = s * (1.0f / 512.0f);
    const float var = ss * (1.0f / 512.0f) - mu * mu;
    const float inv = rsqrtf(var + 1e-6f);

    const int c = threadIdx.x * 2;
    v.x = (v.x - mu) * inv * gamma[c + 0] + beta[c + 0];
    v.y = (v.y - mu) * inv * gamma[c + 1] + beta[c + 1];
    *p = v;
}

// ---------------------------------------------------------------------------
extern "C" void kernel_launch(void* const* d_in, const int* in_sizes, int n_in,
                              void* d_out, int out_size)
{
    const float* in_q  = (const float*)d_in[0];
    const float* in_k  = (const float*)d_in[1];
    const float* in_v  = (const float*)d_in[2];
    const float* w_q   = (const float*)d_in[3];
    const float* w_k   = (const float*)d_in[4];
    const float* w_v   = (const float*)d_in[5];
    const float* w_fc  = (const float*)d_in[6];
    const float* gamma = (const float*)d_in[7];
    const float* beta  = (const float*)d_in[8];
    float* out = (float*)d_out;

    cudaFuncSetAttribute(gemmh<EPI_SCORES>, cudaFuncAttributeMaxDynamicSharedMemorySize, SMEMSZ);
    cudaFuncSetAttribute(gemmh<EPI_PROJ>,   cudaFuncAttributeMaxDynamicSharedMemorySize, SMEMSZ);
    cudaFuncSetAttribute(gemmh<EPI_ATT>,    cudaFuncAttributeMaxDynamicSharedMemorySize, SMEMSZ);
    cudaFuncSetAttribute(gemmh<EPI_FC>,     cudaFuncAttributeMaxDynamicSharedMemorySize, SMEMSZ);

    fp16 *qh, *kh, *vh, *wq, *wk, *wv, *wf;
    fp16 *qhh, *khh, *vhh, *vt, *ph, *at, *sc;
    cudaGetSymbolAddress((void**)&sc, g_sc);
    cudaGetSymbolAddress((void**)&qh, g_q);   cudaGetSymbolAddress((void**)&kh, g_k);
    cudaGetSymbolAddress((void**)&vh, g_v);
    cudaGetSymbolAddress((void**)&wq, g_wq);  cudaGetSymbolAddress((void**)&wk, g_wk);
    cudaGetSymbolAddress((void**)&wv, g_wv);  cudaGetSymbolAddress((void**)&wf, g_wf);
    cudaGetSymbolAddress((void**)&qhh, g_qh); cudaGetSymbolAddress((void**)&khh, g_kh);
    cudaGetSymbolAddress((void**)&vhh, g_vh); cudaGetSymbolAddress((void**)&vt, g_vt);
    cudaGetSymbolAddress((void**)&ph, g_p);   cudaGetSymbolAddress((void**)&at, g_at);

    const int NX = B_ * S_ * D_;     // 4M
    const int NW = HD_ * D_;         // 2M
    conv3_k<<<dim3(NX / 1024, 1, 3), 256>>>(in_q, in_k, in_v, qh, kh, vh, NX);
    conv4_k<<<dim3(NW / 1024, 1, 4), 256>>>(w_q, w_k, w_v, w_fc, wq, wk, wv, wf, NW);

    const float SCALE = 0.044194173824159216f;   // 1/sqrt(512)

    // 1) projections (M=8192, N=4096, K=512) -> heads layout
    const dim3 gp(HD_ / 128, (B_ * S_) / 128, 1);
    gemmh<EPI_PROJ><<<gp, 128, SMEMSZ>>>(qh, wq, nullptr, qhh, nullptr, D_, 0, 0, 1.0f);
    gemmh<EPI_PROJ><<<gp, 128, SMEMSZ>>>(kh, wk, nullptr, khh, nullptr, D_, 0, 0, 1.0f);
    gemmh<EPI_PROJ><<<gp, 128, SMEMSZ>>>(vh, wv, nullptr, vhh, nullptr, D_, 0, 0, 1.0f);

    // 1b) V transpose: (z,s,d) -> (z,d,s) so PV stays row.col
    transp_k<<<dim3(DK_ / 64, S_ / 64, B_ * H_), 256>>>(vhh, vt);

    // 2) scores (per z: M=N=1024, K=512), scaled, fp16 out
    const dim3 gs(S_ / 128, S_ / 128, B_ * H_);
    gemmh<EPI_SCORES><<<gs, 128, SMEMSZ>>>(qhh, khh, nullptr, sc, nullptr,
                                           DK_, (long long)S_ * DK_, (long long)S_ * DK_, SCALE);

    // 3) softmax -> fp16 P
    softmax_k<<<B_ * H_ * S_, 256>>>(sc, ph);

    // 4) P @ V (per z: M=1024, N=512, K=1024; B = V^T)
    const dim3 gv(DK_ / 128, S_ / 128, B_ * H_);
    gemmh<EPI_ATT><<<gv, 128, SMEMSZ>>>(ph, vt, nullptr, at, nullptr,
                                        S_, (long long)S_ * S_, (long long)DK_ * S_, 1.0f);

    // 5) fc + residual (M=8192, N=512, K=4096)
    const dim3 gf(D_ / 128, (B_ * S_) / 128, 1);
    gemmh<EPI_FC><<<gf, 128, SMEMSZ>>>(at, wf, out, nullptr, in_q, HD_, 0, 0, 1.0f);

    // 6) LayerNorm
    ln_k<<<B_ * S_, 256>>>(out, gamma, beta);
}